// round 2
// baseline (speedup 1.0000x reference)
#include <cuda_runtime.h>

// LiquidNeuralNetwork: fused input-projection + sequential Euler scan + output head.
// Shapes: B=256, S=4096, I=32, H=64, O=1.
//
// Algebra:
//   ie[b,t,:] = x[b,t,:] @ Wc^T + cbias,  Wc = W_ih @ W_in (64x32), cbias = bias + W_ih @ b_in
//   h_{t+1}   = h_t + (tanh(h_t) @ W_hh^T + ie_t + 0 - h_t) * (1/tau)   [dt = 1]
//   out[b,t]  = tanh(h_{t+1}) @ W_out^T + b_out
//
// Mapping: 1 CTA per batch chain, 64 threads (thread j owns h[j], W_hh row j and
// Wc row j in registers). tanh history ring in shared -> 1 barrier/step, output
// head batched per 64-step chunk (no per-step reductions).

#define NB   256
#define SEQ  4096
#define NI   32
#define NH   64
#define TC   64            // time-steps per chunk
#define RSTRIDE 68         // padded row stride (floats): 16B-aligned, bank-spread

__device__ float g_Wc[NH * NI];
__device__ float g_cbias[NH];

__global__ void precompute_kernel(const float* __restrict__ W_in,
                                  const float* __restrict__ b_in,
                                  const float* __restrict__ W_ih,
                                  const float* __restrict__ bias)
{
    const int g = threadIdx.x;
    if (g >= NH) return;
    float wih[NH];
#pragma unroll
    for (int h = 0; h < NH; h++) wih[h] = W_ih[g * NH + h];
#pragma unroll 4
    for (int i = 0; i < NI; i++) {
        float s0 = 0.f, s1 = 0.f;
#pragma unroll
        for (int h = 0; h < NH; h += 2) {
            s0 += wih[h + 0] * W_in[(h + 0) * NI + i];
            s1 += wih[h + 1] * W_in[(h + 1) * NI + i];
        }
        g_Wc[g * NI + i] = s0 + s1;
    }
    float cb = bias[g];
#pragma unroll
    for (int h = 0; h < NH; h++) cb += wih[h] * b_in[h];
    g_cbias[g] = cb;
}

__global__ __launch_bounds__(64) void lnn_scan_kernel(
    const float* __restrict__ x,
    const float* __restrict__ W_hh,
    const float* __restrict__ tau,
    const float* __restrict__ W_out,
    const float* __restrict__ b_out,
    float* __restrict__ out)
{
    __shared__ __align__(16) float sh_th[(TC + 1) * RSTRIDE];  // tanh history ring
    __shared__ __align__(16) float sh_x[TC * NI];              // x chunk
    __shared__ float sh_wo[NH];

    const int j = threadIdx.x;   // hidden index this thread owns
    const int b = blockIdx.x;    // batch chain

    // Resident weights
    float Wc[NI], Whh[NH];
#pragma unroll
    for (int i = 0; i < NI; i++) Wc[i] = g_Wc[j * NI + i];
#pragma unroll
    for (int k = 0; k < NH; k++) Whh[k] = W_hh[j * NH + k];
    const float cb   = g_cbias[j];
    const float invt = 1.0f / tau[j];
    const float bo   = b_out[0];
    sh_wo[j] = W_out[j];

    const float4* xg = (const float4*)(x + (size_t)b * SEQ * NI); // 512 float4 per chunk
    float* outb = out + (size_t)b * SEQ;

    // Prefetch chunk 0 into registers (8 x LDG.128 per thread).
    float4 pf[8];
#pragma unroll
    for (int q = 0; q < 8; q++) pf[q] = xg[q * 64 + j];

    float h = 0.f, th = 0.f;   // th = tanh(h), h_0 = 0

    for (int c = 0; c < SEQ / TC; c++) {
        // Commit prefetched x chunk to shared; seed ring row 0 with current th.
#pragma unroll
        for (int q = 0; q < 8; q++) ((float4*)sh_x)[q * 64 + j] = pf[q];
        sh_th[j] = th;
        if (c + 1 < SEQ / TC) {
#pragma unroll
            for (int q = 0; q < 8; q++) pf[q] = xg[(c + 1) * 512 + q * 64 + j];
        }

#pragma unroll 1
        for (int tt = 0; tt < TC; tt++) {
            __syncthreads();   // row tt (and x chunk / sh_wo on first pass) visible

            // z = cbias + tanh(h_t) @ Whh_row_j + x_t @ Wc_row_j  (4 acc chains)
            float z0 = cb, z1 = 0.f, z2 = 0.f, z3 = 0.f;
            const float4* t4 = (const float4*)(sh_th + tt * RSTRIDE);
#pragma unroll
            for (int k = 0; k < NH / 4; k++) {
                float4 v = t4[k];
                z0 += v.x * Whh[4 * k + 0];
                z1 += v.y * Whh[4 * k + 1];
                z2 += v.z * Whh[4 * k + 2];
                z3 += v.w * Whh[4 * k + 3];
            }
            const float4* x4 = (const float4*)(sh_x + tt * NI);
#pragma unroll
            for (int i = 0; i < NI / 4; i++) {
                float4 v = x4[i];
                z0 += v.x * Wc[4 * i + 0];
                z1 += v.y * Wc[4 * i + 1];
                z2 += v.z * Wc[4 * i + 2];
                z3 += v.w * Wc[4 * i + 3];
            }
            const float z = (z0 + z1) + (z2 + z3);

            h  = fmaf(z - h, invt, h);     // Euler step (dt = 1)
            th = tanhf(h);
            sh_th[(tt + 1) * RSTRIDE + j] = th;   // row tt+1 (no WAR: fresh row)
        }
        __syncthreads();   // ring rows 1..TC complete

        // Output head, batched: thread j computes out for time index (c*TC + j)
        {
            const float* row = sh_th + (j + 1) * RSTRIDE;
            float o0 = bo, o1 = 0.f, o2 = 0.f, o3 = 0.f;
#pragma unroll
            for (int k = 0; k < NH; k += 4) {
                o0 += row[k + 0] * sh_wo[k + 0];
                o1 += row[k + 1] * sh_wo[k + 1];
                o2 += row[k + 2] * sh_wo[k + 2];
                o3 += row[k + 3] * sh_wo[k + 3];
            }
            outb[c * TC + j] = (o0 + o1) + (o2 + o3);
        }
        // No barrier needed here: next chunk only rewrites row 0 / sh_x before
        // the step-0 __syncthreads, which orders it against these reads.
    }
}

extern "C" void kernel_launch(void* const* d_in, const int* in_sizes, int n_in,
                              void* d_out, int out_size)
{
    const float* x     = (const float*)d_in[0];
    const float* W_in  = (const float*)d_in[1];
    const float* b_in  = (const float*)d_in[2];
    const float* W_hh  = (const float*)d_in[3];
    const float* W_ih  = (const float*)d_in[4];
    const float* bias  = (const float*)d_in[5];
    const float* tau   = (const float*)d_in[6];
    const float* W_out = (const float*)d_in[7];
    const float* b_out = (const float*)d_in[8];
    float* out = (float*)d_out;

    precompute_kernel<<<1, 64>>>(W_in, b_in, W_ih, bias);
    lnn_scan_kernel<<<NB, 64>>>(x, W_hh, tau, W_out, b_out, out);
}